// round 13
// baseline (speedup 1.0000x reference)
#include <cuda_runtime.h>
#include <cuda_bf16.h>

#define IMAGE_TOKEN_ID 31999
#define BB 4
#define LL 1024
#define DD 2048
#define NUM_VIS 576
#define NEW_LEN (LL - 1 + NUM_VIS)   // 1599
#define D4 (DD / 4)                  // 512 float4 per row
#define MERGED_ROWS (BB * NEW_LEN)   // 6396
#define MERGED_ELEMS (MERGED_ROWS * DD)
#define ROWS_PER_CTA 8
#define ROW_CTAS ((MERGED_ROWS + ROWS_PER_CTA - 1) / ROWS_PER_CTA)  // 800

// Zero source row for the duplicate-scatter case (static -> zero-initialized).
__device__ float4 g_zero[D4];

// Evict-first store: keep the 52 MB output stream from thrashing L2 read lines.
__device__ __forceinline__ void stg_cs(float4* p, float4 v) {
    asm volatile("st.global.cs.v4.f32 [%0], {%1,%2,%3,%4};"
                 :: "l"(p), "f"(v.x), "f"(v.y), "f"(v.z), "f"(v.w) : "memory");
}

// Scan one batch row's 1024 ids with a single int4 load per thread.
__device__ __forceinline__ void scan_row(const int4* __restrict__ row_ids4,
                                         int t, int* s_slot) {
    int4 w = row_ids4[t];                  // ids[4t .. 4t+3]
    int pos = -1;
    if (w.x == IMAGE_TOKEN_ID) pos = 4 * t;
    if (w.y == IMAGE_TOKEN_ID) pos = 4 * t + 1;
    if (w.z == IMAGE_TOKEN_ID) pos = 4 * t + 2;
    if (w.w == IMAGE_TOKEN_ID) pos = 4 * t + 3;
    if (pos >= 0) atomicMax(s_slot, pos);  // exactly one match per row
}

// Route output row (b, j) with image position p to a source pointer.
__device__ __forceinline__ const float4* route_row(
    int b, int j, int p,
    const int* __restrict__ ids,
    const float4* __restrict__ vis,
    const float4* __restrict__ embed)
{
    if (j >= p && j < p + NUM_VIS) {
        return vis + ((size_t)b * NUM_VIS + (j - p)) * D4;
    }
    if (j == 0 && p != 0) {
        // reference's duplicate-scatter: image row's dummy zero-write to slot 0
        // lands after text position 0's write (XLA in-order scatter).
        return g_zero;
    }
    int i = (j < p) ? j : (j - NUM_VIS + 1);
    return embed + (size_t)ids[b * LL + i] * D4;
}

// Single fused kernel. Tail (position_ids) blocks run FIRST so they finish
// inside the memory-bound phase. Then one CTA per EIGHT output rows; 256
// threads, int4 ids-scan, 16 front-batched LDG.128 + 16 evict-first STG.128.
__global__ void __launch_bounds__(256) merge_kernel(
    const int*    __restrict__ ids,    // [B, L]
    const float4* __restrict__ vis,    // [B, NUM_VIS, D/4]
    const float4* __restrict__ embed,  // [32768, D/4]
    float4*       __restrict__ out,    // [B, NEW_LEN, D/4] (+ tail)
    int tail_n, int tail_blocks)
{
    int blk = blockIdx.x;
    int t = threadIdx.x;

    if (blk < tail_blocks) {
        // position_ids tail: broadcast arange(NEW_LEN), as output dtype (fp32)
        int i = blk * 256 + t;
        if (i < tail_n) {
            float* tail = (float*)out + (size_t)MERGED_ELEMS;
            tail[i] = (float)(i % NEW_LEN);
        }
        return;
    }
    blk -= tail_blocks;

    int row0 = blk * ROWS_PER_CTA;
    int b_first = row0 / NEW_LEN;
    int last_row = row0 + ROWS_PER_CTA - 1;
    if (last_row >= MERGED_ROWS) last_row = MERGED_ROWS - 1;
    int b_last = last_row / NEW_LEN;                     // <= b_first + 1

    // ---- find image-token positions for the (1 or 2) batch rows involved ----
    __shared__ int s_p[2];
    if (t < 2) s_p[t] = 0;
    __syncthreads();
    scan_row((const int4*)(ids + b_first * LL), t, &s_p[0]);
    if (b_last != b_first) {
        scan_row((const int4*)(ids + b_last * LL), t, &s_p[1]);
    }
    __syncthreads();
    int p0 = s_p[0];
    int p1 = s_p[1];

    // ---- route all rows, then pipelined loads / stores ----
    const float4* src[ROWS_PER_CTA];
    #pragma unroll
    for (int r = 0; r < ROWS_PER_CTA; r++) {
        int row = row0 + r;
        if (row < MERGED_ROWS) {
            int b = row / NEW_LEN;
            int j = row - b * NEW_LEN;
            int p = (b == b_first) ? p0 : p1;
            src[r] = route_row(b, j, p, ids, vis, embed);
        } else {
            src[r] = g_zero;   // harmless load target; store guarded below
        }
    }

    float4 v[ROWS_PER_CTA][2];
    #pragma unroll
    for (int r = 0; r < ROWS_PER_CTA; r++) {
        v[r][0] = src[r][t];
        v[r][1] = src[r][t + 256];
    }

    float4* dst = out + (size_t)row0 * D4;
    #pragma unroll
    for (int r = 0; r < ROWS_PER_CTA; r++) {
        if (row0 + r < MERGED_ROWS) {
            stg_cs(dst + r * D4 + t,       v[r][0]);
            stg_cs(dst + r * D4 + t + 256, v[r][1]);
        }
    }
}

extern "C" void kernel_launch(void* const* d_in, const int* in_sizes, int n_in,
                              void* d_out, int out_size) {
    const int*    ids   = (const int*)d_in[0];            // [B, L] int32
    const float4* vis   = (const float4*)d_in[1];         // [B, NUM_VIS, D]
    const float4* embed = (const float4*)d_in[2];         // [32768, D]

    int tail_n = out_size - MERGED_ELEMS;
    if (tail_n < 0) tail_n = 0;
    int tail_blocks = (tail_n + 255) / 256;

    merge_kernel<<<ROW_CTAS + tail_blocks, 256>>>(
        ids, vis, embed, (float4*)d_out, tail_n, tail_blocks);
}